// round 12
// baseline (speedup 1.0000x reference)
#include <cuda_runtime.h>
#include <cuda_fp16.h>
#include <cstdint>

#define N_NODES 4096
#define K_TOT   16384
#define OUT64   64

#define TILE_M  128
#define KC      32
#define SPLIT   16
#define KSPAN   (K_TOT / SPLIT)   // 1024
#define NCH     (KSPAN / KC)      // 32

// B^T in fp16: g_B[o][k], 64 x 16384 row-major (o = r*4+kch, k = n*4+c)
__device__ unsigned short g_B[64 * K_TOT];

// ---------------------------------------------------------------------------
__device__ __forceinline__ uint32_t smem_u32(const void* p) {
    uint32_t a;
    asm("{ .reg .u64 t; cvta.to.shared.u64 t, %1; cvt.u32.u64 %0, t; }"
        : "=r"(a) : "l"(p));
    return a;
}

#define CP_ASYNC16(dst, src) \
    asm volatile("cp.async.cg.shared.global [%0], [%1], 16;" :: "r"(dst), "l"(src))
#define CP_COMMIT() asm volatile("cp.async.commit_group;" ::: "memory")
#define CP_WAIT2()  asm volatile("cp.async.wait_group 2;" ::: "memory")
#define CP_WAIT1()  asm volatile("cp.async.wait_group 1;" ::: "memory")
#define CP_WAIT0()  asm volatile("cp.async.wait_group 0;" ::: "memory")

#define LDSM_X4(r, addr) \
    asm volatile("ldmatrix.sync.aligned.m8n8.x4.shared.b16 {%0,%1,%2,%3}, [%4];" \
        : "=r"((r)[0]), "=r"((r)[1]), "=r"((r)[2]), "=r"((r)[3]) : "r"(addr))

#define LDS64F(f0, f1, addr) \
    asm volatile("ld.shared.v2.f32 {%0,%1}, [%2];" : "=f"(f0), "=f"(f1) : "r"(addr))

#define MMA_F16(d, a, b0, b1) \
    asm volatile("mma.sync.aligned.m16n8k16.row.col.f32.f16.f16.f32 " \
        "{%0,%1,%2,%3}, {%4,%5,%6,%7}, {%8,%9}, {%0,%1,%2,%3};" \
        : "+f"((d)[0]), "+f"((d)[1]), "+f"((d)[2]), "+f"((d)[3]) \
        : "r"((a)[0]), "r"((a)[1]), "r"((a)[2]), "r"((a)[3]), "r"(b0), "r"(b1))

// pack two f32 -> f16x2 (x in LOW half, y in HIGH half)
#define F16X2(u, x, y) \
    asm("cvt.rn.f16x2.f32 %0, %1, %2;" : "=r"(u) : "f"(y), "f"(x))

// ---------------------------------------------------------------------------
// build_gemm: g_B^T[n][(o,c)] = features[n,:] @ B2,
//   B2[(j,e)][m=(r,kk,c)] = w[j, r, (kk - c - e) & 3]   (fp16 MMA, K=256)
// ---------------------------------------------------------------------------
#define B2PITCH 528u

__global__ void __launch_bounds__(256) build_gemm(
    const float* __restrict__ features,   // [4096, 256] = [n][(j,e)]
    const float* __restrict__ weight)     // [64, 16, 4]  = [j][r][shift]
{
    __shared__ float s_w[4096];
    __shared__ __align__(16) char s_b2[64 * B2PITCH];

    const int tid  = threadIdx.x;
    const int wid  = tid >> 5;
    const int lane = tid & 31;
    const int g    = lane >> 2;
    const int t    = lane & 3;
    const int n0   = blockIdx.x * 128;
    const int m0   = blockIdx.y * 64;

    #pragma unroll
    for (int i = 0; i < 4; i++)
        ((float4*)s_w)[tid + i * 256] = ((const float4*)weight)[tid + i * 256];
    __syncthreads();

    #pragma unroll
    for (int idx = tid; idx < 64 * 256; idx += 256) {
        const int mloc = idx >> 8, jc = idx & 255;
        const int m = m0 + mloc;
        const int r = m >> 4, kk = (m >> 2) & 3, c = m & 3;
        const int j = jc >> 2, e = jc & 3;
        const float val = s_w[j * 64 + r * 4 + ((kk - c - e) & 3)];
        *(unsigned short*)(s_b2 + mloc * B2PITCH + jc * 2) =
            __half_as_ushort(__float2half_rn(val));
    }
    __syncthreads();

    const uint32_t base = smem_u32(s_b2);
    const uint32_t lrow = (uint32_t)(lane & 15);
    const uint32_t lkb  = (uint32_t)(lane & 16);

    float acc[8][4];
    #pragma unroll
    for (int nt = 0; nt < 8; nt++)
        #pragma unroll
        for (int q = 0; q < 4; q++) acc[nt][q] = 0.f;

    const float* fp = features + (size_t)(n0 + wid * 16 + g) * 256 + 2 * t;

    #pragma unroll 4
    for (int ks = 0; ks < 16; ks++) {
        const float* q0 = fp + ks * 16;
        float2 p0 = *(const float2*)(q0);
        float2 p1 = *(const float2*)(q0 + 8 * 256);
        float2 p2 = *(const float2*)(q0 + 8);
        float2 p3 = *(const float2*)(q0 + 8 * 256 + 8);
        uint32_t af[4];
        F16X2(af[0], p0.x, p0.y);
        F16X2(af[1], p1.x, p1.y);
        F16X2(af[2], p2.x, p2.y);
        F16X2(af[3], p3.x, p3.y);

        #pragma unroll
        for (int nt2 = 0; nt2 < 4; nt2++) {
            uint32_t baddr = base + (uint32_t)(nt2 * 16 + lrow) * B2PITCH
                           + (uint32_t)(ks * 32) + lkb;
            uint32_t bb[4];
            LDSM_X4(bb, baddr);
            MMA_F16(acc[nt2 * 2],     af, bb[0], bb[2]);
            MMA_F16(acc[nt2 * 2 + 1], af, bb[1], bb[3]);
        }
    }

    const int n = n0 + wid * 16 + g;
    #pragma unroll
    for (int nt = 0; nt < 8; nt++) {
        const int m = m0 + nt * 8 + 2 * t;
        const int o = m >> 2, c = m & 3;
        uint32_t lo, hi;
        F16X2(lo, acc[nt][0], acc[nt][1]);
        F16X2(hi, acc[nt][2], acc[nt][3]);
        *(uint32_t*)((char*)g_B + ((size_t)o * K_TOT + n * 4 + c) * 2)       = lo;
        *(uint32_t*)((char*)g_B + ((size_t)o * K_TOT + (n + 8) * 4 + c) * 2) = hi;
    }
}

// ---------------------------------------------------------------------------
// Main gemm smem (dynamic), 4-stage pipeline:
//   A: 4 x 16384 (128 rows x 128B, XOR-swizzled 16B chunks)
//   B: 4 x 5120  (64 rows x 80B pitch)
// ---------------------------------------------------------------------------
#define ABUF   16384u
#define SM_B0  65536u
#define BPITCH 80u
#define BBUF   5120u
#define SMEM_BYTES (65536 + 4 * 5120)

__device__ __forceinline__ void loadA(uint32_t dst, const float* __restrict__ adj,
                                      int i0, int kk0, int tid)
{
    const char* src = (const char*)(adj + (size_t)i0 * K_TOT + kk0);
    #pragma unroll
    for (int i = 0; i < 4; i++) {
        int e = tid + i * 256;               // 1024 16B chunks
        int row = e >> 3, f = e & 7;
        uint32_t d = dst + (uint32_t)row * 128u + (uint32_t)((f ^ (row & 7)) << 4);
        CP_ASYNC16(d, src + (size_t)row * (K_TOT * 4) + f * 16);
    }
}

__device__ __forceinline__ void loadB(uint32_t dst, int kk0, int tid)
{
    const int row = tid >> 2, seg = tid & 3;   // 64 rows x 4 16B segs
    uint32_t d = dst + (uint32_t)row * BPITCH + (uint32_t)seg * 16u;
    const char* s = (const char*)g_B + ((size_t)row * K_TOT + kk0) * 2 + seg * 16;
    CP_ASYNC16(d, s);
}

// ---------------------------------------------------------------------------
// Main GEMM: out[i][o] += sum_k adj[i][k] * Bt[o][k]  (fp16 MMA, fp32 accum)
// 4-stage cp.async pipeline (3 chunks in flight), correct tail drain:
// before consuming chunk s, wait_group min(2, NCH-1-s).
// ---------------------------------------------------------------------------
__global__ void __launch_bounds__(256, 2) gemm_mma(
    const float* __restrict__ adj, float* __restrict__ out)
{
    extern __shared__ __align__(16) char sm[];
    const uint32_t base = smem_u32(sm);

    const int tid  = threadIdx.x;
    const int wid  = tid >> 5;
    const int lane = tid & 31;
    const int g    = lane >> 2;
    const int t    = lane & 3;
    const int i0    = blockIdx.x * TILE_M;
    const int kbase = blockIdx.y * KSPAN;

    float acc[8][4];
    #pragma unroll
    for (int nt = 0; nt < 8; nt++)
        #pragma unroll
        for (int q = 0; q < 4; q++) acc[nt][q] = 0.f;

    // prologue: commit chunks 0,1,2 as separate groups
    #pragma unroll
    for (int s = 0; s < 3; s++) {
        loadA(base + (uint32_t)s * ABUF, adj, i0, kbase + s * KC, tid);
        loadB(base + SM_B0 + (uint32_t)s * BBUF, kbase + s * KC, tid);
        CP_COMMIT();
    }

    const uint32_t lrow = (uint32_t)(lane & 15);
    const uint32_t lkb  = (uint32_t)(lane & 16);
    const uint32_t ar0  = (uint32_t)(wid * 16 + g) * 128u + (uint32_t)((t & 1) << 3);
    const uint32_t xg   = (uint32_t)g << 4;           // swizzle XOR (row&7 == g)
    const uint32_t tch  = (uint32_t)(t >> 1) << 4;    // (t>>1) chunk offset

    for (int s = 0; s < NCH; s++) {
        // wait until chunk s has arrived: pending groups are {s..min(s+2,NCH-1)}
        if (s + 2 < NCH)      { CP_WAIT2(); }
        else if (s + 1 < NCH) { CP_WAIT1(); }
        else                  { CP_WAIT0(); }
        __syncthreads();
        if (s + 3 < NCH) {
            const int nb = (s + 3) & 3;    // == (s-1)&3: reads finished last iter
            loadA(base + (uint32_t)nb * ABUF, adj, i0, kbase + (s + 3) * KC, tid);
            loadB(base + SM_B0 + (uint32_t)nb * BBUF, kbase + (s + 3) * KC, tid);
            CP_COMMIT();
        }

        const uint32_t sa = base + (uint32_t)(s & 3) * ABUF;
        const uint32_t sb = base + SM_B0 + (uint32_t)(s & 3) * BBUF;

        #pragma unroll
        for (int ks = 0; ks < 2; ks++) {
            // A fragments from swizzled smem: 4 x LDS.64 (2 wavefronts each)
            const uint32_t c0 = ((uint32_t)(ks * 4) << 4) + tch;   // chunk 4ks + t>>1
            const uint32_t c2 = c0 + (2u << 4);                     // +2 chunks (k+8)
            float x0, y0, x1, y1, x2, y2, x3, y3;
            LDS64F(x0, y0, sa + ar0         + (c0 ^ xg));
            LDS64F(x1, y1, sa + ar0 + 1024u + (c0 ^ xg));
            LDS64F(x2, y2, sa + ar0         + (c2 ^ xg));
            LDS64F(x3, y3, sa + ar0 + 1024u + (c2 ^ xg));
            uint32_t af[4];
            F16X2(af[0], x0, y0);
            F16X2(af[1], x1, y1);
            F16X2(af[2], x2, y2);
            F16X2(af[3], x3, y3);

            #pragma unroll
            for (int nt2 = 0; nt2 < 4; nt2++) {
                uint32_t baddr = sb + (uint32_t)(nt2 * 16 + lrow) * BPITCH
                               + (uint32_t)(ks * 32) + lkb;
                uint32_t bb[4];
                LDSM_X4(bb, baddr);
                MMA_F16(acc[nt2 * 2],     af, bb[0], bb[2]);
                MMA_F16(acc[nt2 * 2 + 1], af, bb[1], bb[3]);
            }
        }
    }

    // RED epilogue onto bias-seeded out
    const int r0 = i0 + wid * 16 + g;
    float* p0 = out + (size_t)r0 * 64;
    float* p1 = out + (size_t)(r0 + 8) * 64;
    #pragma unroll
    for (int nt = 0; nt < 8; nt++) {
        const int c0 = nt * 8 + 2 * t;
        atomicAdd(p0 + c0,     acc[nt][0]);
        atomicAdd(p0 + c0 + 1, acc[nt][1]);
        atomicAdd(p1 + c0,     acc[nt][2]);
        atomicAdd(p1 + c0 + 1, acc[nt][3]);
    }
}

// ---------------------------------------------------------------------------
extern "C" void kernel_launch(void* const* d_in, const int* in_sizes, int n_in,
                              void* d_out, int out_size)
{
    const float* features = (const float*)d_in[0];
    const float* adj      = (const float*)d_in[1];
    const float* weight   = (const float*)d_in[2];
    const float* bias     = (const float*)d_in[3];
    float* out            = (float*)d_out;
    (void)in_sizes; (void)n_in; (void)out_size;

    cudaFuncSetAttribute(gemm_mma, cudaFuncAttributeMaxDynamicSharedMemorySize, SMEM_BYTES);

    // seed out with bias (graph-capturable async D2D copy)
    cudaMemcpyAsync(out, bias, (size_t)N_NODES * OUT64 * sizeof(float),
                    cudaMemcpyDeviceToDevice);
    build_gemm<<<dim3(32, 4), 256>>>(features, weight);
    gemm_mma<<<dim3(N_NODES / TILE_M, SPLIT), 256, SMEM_BYTES>>>(adj, out);
}

// round 13
// speedup vs baseline: 1.0644x; 1.0644x over previous
#include <cuda_runtime.h>
#include <cuda_fp16.h>
#include <cstdint>

#define N_NODES 4096
#define K_TOT   16384
#define OUT64   64

#define TILE_M  64
#define NTHR    128
#define KC      32
#define SPLIT   8
#define KSPAN   (K_TOT / SPLIT)   // 2048
#define NCH     (KSPAN / KC)      // 64

// B^T in fp16: g_B[o][k], 64 x 16384 row-major (o = r*4+kch, k = n*4+c)
__device__ unsigned short g_B[64 * K_TOT];

// ---------------------------------------------------------------------------
__device__ __forceinline__ uint32_t smem_u32(const void* p) {
    uint32_t a;
    asm("{ .reg .u64 t; cvta.to.shared.u64 t, %1; cvt.u32.u64 %0, t; }"
        : "=r"(a) : "l"(p));
    return a;
}

#define CP_ASYNC16(dst, src) \
    asm volatile("cp.async.cg.shared.global [%0], [%1], 16;" :: "r"(dst), "l"(src))
#define CP_COMMIT() asm volatile("cp.async.commit_group;" ::: "memory")
#define CP_WAIT1()  asm volatile("cp.async.wait_group 1;" ::: "memory")
#define CP_WAIT0()  asm volatile("cp.async.wait_group 0;" ::: "memory")

#define LDSM_X4(r, addr) \
    asm volatile("ldmatrix.sync.aligned.m8n8.x4.shared.b16 {%0,%1,%2,%3}, [%4];" \
        : "=r"((r)[0]), "=r"((r)[1]), "=r"((r)[2]), "=r"((r)[3]) : "r"(addr))

#define LDS64F(f0, f1, addr) \
    asm volatile("ld.shared.v2.f32 {%0,%1}, [%2];" : "=f"(f0), "=f"(f1) : "r"(addr))

#define MMA_F16(d, a, b0, b1) \
    asm volatile("mma.sync.aligned.m16n8k16.row.col.f32.f16.f16.f32 " \
        "{%0,%1,%2,%3}, {%4,%5,%6,%7}, {%8,%9}, {%0,%1,%2,%3};" \
        : "+f"((d)[0]), "+f"((d)[1]), "+f"((d)[2]), "+f"((d)[3]) \
        : "r"((a)[0]), "r"((a)[1]), "r"((a)[2]), "r"((a)[3]), "r"(b0), "r"(b1))

// pack two f32 -> f16x2 (x in LOW half, y in HIGH half)
#define F16X2(u, x, y) \
    asm("cvt.rn.f16x2.f32 %0, %1, %2;" : "=r"(u) : "f"(y), "f"(x))

// ---------------------------------------------------------------------------
// build_gemm: g_B^T[n][(o,c)] = features[n,:] @ B2,
//   B2[(j,e)][m=(r,kk,c)] = w[j, r, (kk - c - e) & 3]   (fp16 MMA, K=256)
// ---------------------------------------------------------------------------
#define B2PITCH 528u

__global__ void __launch_bounds__(256) build_gemm(
    const float* __restrict__ features,   // [4096, 256] = [n][(j,e)]
    const float* __restrict__ weight)     // [64, 16, 4]  = [j][r][shift]
{
    __shared__ float s_w[4096];
    __shared__ __align__(16) char s_b2[64 * B2PITCH];

    const int tid  = threadIdx.x;
    const int wid  = tid >> 5;
    const int lane = tid & 31;
    const int g    = lane >> 2;
    const int t    = lane & 3;
    const int n0   = blockIdx.x * 128;
    const int m0   = blockIdx.y * 64;

    #pragma unroll
    for (int i = 0; i < 4; i++)
        ((float4*)s_w)[tid + i * 256] = ((const float4*)weight)[tid + i * 256];
    __syncthreads();

    #pragma unroll
    for (int idx = tid; idx < 64 * 256; idx += 256) {
        const int mloc = idx >> 8, jc = idx & 255;
        const int m = m0 + mloc;
        const int r = m >> 4, kk = (m >> 2) & 3, c = m & 3;
        const int j = jc >> 2, e = jc & 3;
        const float val = s_w[j * 64 + r * 4 + ((kk - c - e) & 3)];
        *(unsigned short*)(s_b2 + mloc * B2PITCH + jc * 2) =
            __half_as_ushort(__float2half_rn(val));
    }
    __syncthreads();

    const uint32_t base = smem_u32(s_b2);
    const uint32_t lrow = (uint32_t)(lane & 15);
    const uint32_t lkb  = (uint32_t)(lane & 16);

    float acc[8][4];
    #pragma unroll
    for (int nt = 0; nt < 8; nt++)
        #pragma unroll
        for (int q = 0; q < 4; q++) acc[nt][q] = 0.f;

    const float* fp = features + (size_t)(n0 + wid * 16 + g) * 256 + 2 * t;

    #pragma unroll 4
    for (int ks = 0; ks < 16; ks++) {
        const float* q0 = fp + ks * 16;
        float2 p0 = *(const float2*)(q0);
        float2 p1 = *(const float2*)(q0 + 8 * 256);
        float2 p2 = *(const float2*)(q0 + 8);
        float2 p3 = *(const float2*)(q0 + 8 * 256 + 8);
        uint32_t af[4];
        F16X2(af[0], p0.x, p0.y);
        F16X2(af[1], p1.x, p1.y);
        F16X2(af[2], p2.x, p2.y);
        F16X2(af[3], p3.x, p3.y);

        #pragma unroll
        for (int nt2 = 0; nt2 < 4; nt2++) {
            uint32_t baddr = base + (uint32_t)(nt2 * 16 + lrow) * B2PITCH
                           + (uint32_t)(ks * 32) + lkb;
            uint32_t bb[4];
            LDSM_X4(bb, baddr);
            MMA_F16(acc[nt2 * 2],     af, bb[0], bb[2]);
            MMA_F16(acc[nt2 * 2 + 1], af, bb[1], bb[3]);
        }
    }

    const int n = n0 + wid * 16 + g;
    #pragma unroll
    for (int nt = 0; nt < 8; nt++) {
        const int m = m0 + nt * 8 + 2 * t;
        const int o = m >> 2, c = m & 3;
        uint32_t lo, hi;
        F16X2(lo, acc[nt][0], acc[nt][1]);
        F16X2(hi, acc[nt][2], acc[nt][3]);
        *(uint32_t*)((char*)g_B + ((size_t)o * K_TOT + n * 4 + c) * 2)       = lo;
        *(uint32_t*)((char*)g_B + ((size_t)o * K_TOT + (n + 8) * 4 + c) * 2) = hi;
    }
}

// ---------------------------------------------------------------------------
// Main gemm smem (dynamic), 3-stage pipeline, small CTA (64 rows, 128 thr):
//   A: 3 x 8192 (64 rows x 128B, XOR-swizzled 16B chunks)
//   B: 3 x 5120 (64 rows x 80B pitch)
// ---------------------------------------------------------------------------
#define ABUF   8192u
#define SM_B0  24576u
#define BPITCH 80u
#define BBUF   5120u
#define SMEM_BYTES (24576 + 3 * 5120)

__device__ __forceinline__ void loadA(uint32_t dst, const float* __restrict__ adj,
                                      int i0, int kk0, int tid)
{
    const char* src = (const char*)(adj + (size_t)i0 * K_TOT + kk0);
    #pragma unroll
    for (int i = 0; i < 4; i++) {
        int e = tid + i * NTHR;              // 512 16B chunks
        int row = e >> 3, f = e & 7;
        uint32_t d = dst + (uint32_t)row * 128u + (uint32_t)((f ^ (row & 7)) << 4);
        CP_ASYNC16(d, src + (size_t)row * (K_TOT * 4) + f * 16);
    }
}

__device__ __forceinline__ void loadB(uint32_t dst, int kk0, int tid)
{
    #pragma unroll
    for (int i = 0; i < 2; i++) {
        int e = tid + i * NTHR;              // 256 16B segs (64 rows x 4)
        int row = e >> 2, seg = e & 3;
        uint32_t d = dst + (uint32_t)row * BPITCH + (uint32_t)seg * 16u;
        const char* s = (const char*)g_B + ((size_t)row * K_TOT + kk0) * 2 + seg * 16;
        CP_ASYNC16(d, s);
    }
}

// ---------------------------------------------------------------------------
// Main GEMM: out[i][o] += sum_k adj[i][k] * Bt[o][k]  (fp16 MMA, fp32 accum)
// TILE_M=64, 4 warps; 3-stage pipeline with correct drain; all CTAs resident.
// ---------------------------------------------------------------------------
__global__ void __launch_bounds__(NTHR, 5) gemm_mma(
    const float* __restrict__ adj, float* __restrict__ out)
{
    extern __shared__ __align__(16) char sm[];
    const uint32_t base = smem_u32(sm);

    const int tid  = threadIdx.x;
    const int wid  = tid >> 5;
    const int lane = tid & 31;
    const int g    = lane >> 2;
    const int t    = lane & 3;
    const int i0    = blockIdx.x * TILE_M;
    const int kbase = blockIdx.y * KSPAN;

    float acc[8][4];
    #pragma unroll
    for (int nt = 0; nt < 8; nt++)
        #pragma unroll
        for (int q = 0; q < 4; q++) acc[nt][q] = 0.f;

    // prologue: commit chunks 0,1 as separate groups
    #pragma unroll
    for (int s = 0; s < 2; s++) {
        loadA(base + (uint32_t)s * ABUF, adj, i0, kbase + s * KC, tid);
        loadB(base + SM_B0 + (uint32_t)s * BBUF, kbase + s * KC, tid);
        CP_COMMIT();
    }

    const uint32_t lrow = (uint32_t)(lane & 15);
    const uint32_t lkb  = (uint32_t)(lane & 16);
    const uint32_t ar0  = (uint32_t)(wid * 16 + g) * 128u + (uint32_t)((t & 1) << 3);
    const uint32_t xg   = (uint32_t)g << 4;           // swizzle XOR (row&7 == g)
    const uint32_t tch  = (uint32_t)(t >> 1) << 4;    // (t>>1) chunk offset

    int b = 0;                                        // buffer index of chunk s
    for (int s = 0; s < NCH; s++) {
        // pending groups: {s .. min(s+1, NCH-1)}
        if (s + 1 < NCH) { CP_WAIT1(); } else { CP_WAIT0(); }
        __syncthreads();
        if (s + 2 < NCH) {
            const int nb = (b + 2 >= 3) ? b - 1 : b + 2;   // (s+2) % 3
            loadA(base + (uint32_t)nb * ABUF, adj, i0, kbase + (s + 2) * KC, tid);
            loadB(base + SM_B0 + (uint32_t)nb * BBUF, kbase + (s + 2) * KC, tid);
            CP_COMMIT();
        }

        const uint32_t sa = base + (uint32_t)b * ABUF;
        const uint32_t sb = base + SM_B0 + (uint32_t)b * BBUF;

        #pragma unroll
        for (int ks = 0; ks < 2; ks++) {
            // A fragments from swizzled smem: 4 x LDS.64 (2 wavefronts each)
            const uint32_t c0 = ((uint32_t)(ks * 4) << 4) + tch;   // chunk 4ks + t>>1
            const uint32_t c2 = c0 + (2u << 4);                     // +2 chunks (k+8)
            float x0, y0, x1, y1, x2, y2, x3, y3;
            LDS64F(x0, y0, sa + ar0         + (c0 ^ xg));
            LDS64F(x1, y1, sa + ar0 + 1024u + (c0 ^ xg));
            LDS64F(x2, y2, sa + ar0         + (c2 ^ xg));
            LDS64F(x3, y3, sa + ar0 + 1024u + (c2 ^ xg));
            uint32_t af[4];
            F16X2(af[0], x0, y0);
            F16X2(af[1], x1, y1);
            F16X2(af[2], x2, y2);
            F16X2(af[3], x3, y3);

            #pragma unroll
            for (int nt2 = 0; nt2 < 4; nt2++) {
                uint32_t baddr = sb + (uint32_t)(nt2 * 16 + lrow) * BPITCH
                               + (uint32_t)(ks * 32) + lkb;
                uint32_t bb[4];
                LDSM_X4(bb, baddr);
                MMA_F16(acc[nt2 * 2],     af, bb[0], bb[2]);
                MMA_F16(acc[nt2 * 2 + 1], af, bb[1], bb[3]);
            }
        }
        b = (b + 1 >= 3) ? 0 : b + 1;
    }

    // RED epilogue onto bias-seeded out
    const int r0 = i0 + wid * 16 + g;
    float* p0 = out + (size_t)r0 * 64;
    float* p1 = out + (size_t)(r0 + 8) * 64;
    #pragma unroll
    for (int nt = 0; nt < 8; nt++) {
        const int c0 = nt * 8 + 2 * t;
        atomicAdd(p0 + c0,     acc[nt][0]);
        atomicAdd(p0 + c0 + 1, acc[nt][1]);
        atomicAdd(p1 + c0,     acc[nt][2]);
        atomicAdd(p1 + c0 + 1, acc[nt][3]);
    }
}

// ---------------------------------------------------------------------------
extern "C" void kernel_launch(void* const* d_in, const int* in_sizes, int n_in,
                              void* d_out, int out_size)
{
    const float* features = (const float*)d_in[0];
    const float* adj      = (const float*)d_in[1];
    const float* weight   = (const float*)d_in[2];
    const float* bias     = (const float*)d_in[3];
    float* out            = (float*)d_out;
    (void)in_sizes; (void)n_in; (void)out_size;

    cudaFuncSetAttribute(gemm_mma, cudaFuncAttributeMaxDynamicSharedMemorySize, SMEM_BYTES);

    // seed out with bias (graph-capturable async D2D copy)
    cudaMemcpyAsync(out, bias, (size_t)N_NODES * OUT64 * sizeof(float),
                    cudaMemcpyDeviceToDevice);
    build_gemm<<<dim3(32, 4), 256>>>(features, weight);
    gemm_mma<<<dim3(N_NODES / TILE_M, SPLIT), NTHR, SMEM_BYTES>>>(adj, out);
}